// round 8
// baseline (speedup 1.0000x reference)
#include <cuda_runtime.h>
#include <cuda_bf16.h>
#include <cstdint>

// ---------------- problem constants (registry shapes) ----------------
#define NN      10000          // nodes per graph
#define EMAXE   320000         // edges (without self loops)
#define E2MAX   (EMAXE + NN)   // + self loops
#define BBMAX   4              // batch
#define DEGCAP  128            // padded-CSR capacity (max degree ~60 => 12 sigma safe)

// ---------------- device scratch (no allocations allowed) -------------
__device__ int   g_esrc[NN * DEGCAP];   // padded CSR: src per slot
__device__ int   g_count[NN];
__device__ int   g_is64;
__device__ float g_h0 [BBMAX * NN * 256];   // layer0 pre-attention features (fp32)
__device__ float g_h1 [BBMAX * NN * 128];   // layer1 pre-attention features (fp32)
__device__ float g_als[BBMAX * NN];
__device__ float g_ald[BBMAX * NN];
// bf16 hi/lo pre-split operands
__device__ __nv_bfloat16 g_xh [BBMAX * NN * 256];
__device__ __nv_bfloat16 g_xl [BBMAX * NN * 256];
__device__ __nv_bfloat16 g_hidh[BBMAX * NN * 256];  // layer0 output, split
__device__ __nv_bfloat16 g_hidl[BBMAX * NN * 256];
__device__ __nv_bfloat16 g_wh0[256 * 256];
__device__ __nv_bfloat16 g_wl0[256 * 256];
__device__ __nv_bfloat16 g_wh1[128 * 256];
__device__ __nv_bfloat16 g_wl1[128 * 256];

// ---------------- edge preprocessing ----------------------------------

// fused: all blocks zero counts; block 0 lane 0 also detects int64 vs int32
__global__ void zerodetect_kernel(const unsigned int* __restrict__ w, int n) {
    int i = blockIdx.x * blockDim.x + threadIdx.x;
    if (i < n) g_count[i] = 0;
    if (blockIdx.x == 0 && threadIdx.x == 0) {
        int ok = 1;
        for (int k = 1; k < 256; k += 2) {
            if (w[k] != 0u) { ok = 0; break; }
        }
        g_is64 = ok;
    }
}

// one-pass padded-CSR build (incl. self loops)
__global__ void convert_scatter_kernel(const void* __restrict__ edges, int E, int Nn) {
    int i = blockIdx.x * blockDim.x + threadIdx.x;
    int E2 = E + Nn;
    if (i >= E2) return;
    int s, d;
    if (i < E) {
        if (g_is64) {
            const long long* p = (const long long*)edges;
            s = (int)p[i];
            d = (int)p[E + i];
        } else {
            const int* p = (const int*)edges;
            s = p[i];
            d = p[E + i];
        }
    } else {
        s = d = i - E;
    }
    int pos = atomicAdd(&g_count[d], 1);
    g_esrc[d * DEGCAP + pos] = s;
}

// ---------------- fused fp32 -> bf16 hi/lo splits (x, W0, W1) ----------
__global__ void split3_kernel(const float* __restrict__ s0, __nv_bfloat16* h0p, __nv_bfloat16* l0p, int n0,
                              const float* __restrict__ s1, __nv_bfloat16* h1p, __nv_bfloat16* l1p, int n1,
                              const float* __restrict__ s2, __nv_bfloat16* h2p, __nv_bfloat16* l2p, int n2) {
    int i = blockIdx.x * blockDim.x + threadIdx.x;
    const float* src; __nv_bfloat16 *ph, *pl;
    if (i < n0)               { src = s0; ph = h0p; pl = l0p; }
    else if ((i -= n0) < n1)  { src = s1; ph = h1p; pl = l1p; }
    else if ((i -= n1) < n2)  { src = s2; ph = h2p; pl = l2p; }
    else return;
    float4 v = ((const float4*)src)[i];
    float f[4] = {v.x, v.y, v.z, v.w};
    __nv_bfloat16 h[4], l[4];
#pragma unroll
    for (int q = 0; q < 4; q++) {
        h[q] = __float2bfloat16(f[q]);
        l[q] = __float2bfloat16(f[q] - __bfloat162float(h[q]));
    }
    ((uint2*)ph)[i] = *(uint2*)h;
    ((uint2*)pl)[i] = *(uint2*)l;
}

// ---------------- bf16x3 split-precision tensor-core GEMM --------------
// C[M][N] = A[M][K] * W[N][K]^T, pre-split bf16 hi/lo, 3 mma terms, k16,
// ldmatrix fragments, 3-stage cp.async ring, 8 warps x (32x64) warp tiles.

#define MMA16(c, a, b)                                                        \
    asm volatile(                                                             \
        "mma.sync.aligned.m16n8k16.row.col.f32.bf16.bf16.f32 "                \
        "{%0,%1,%2,%3},{%4,%5,%6,%7},{%8,%9},{%0,%1,%2,%3};"                  \
        : "+f"((c)[0]), "+f"((c)[1]), "+f"((c)[2]), "+f"((c)[3])              \
        : "r"((a)[0]), "r"((a)[1]), "r"((a)[2]), "r"((a)[3]),                 \
          "r"((b)[0]), "r"((b)[1]))

#define LDSM4(R, addr)                                                        \
    asm volatile(                                                             \
        "ldmatrix.sync.aligned.m8n8.x4.shared.b16 {%0,%1,%2,%3}, [%4];"       \
        : "=r"((R)[0]), "=r"((R)[1]), "=r"((R)[2]), "=r"((R)[3])              \
        : "r"(addr))

#define CPA16(dst, src, sz)                                                   \
    asm volatile("cp.async.cg.shared.global [%0], [%1], 16, %2;"              \
                 :: "r"(dst), "l"(src), "r"(sz) : "memory")
#define CPA_COMMIT() asm volatile("cp.async.commit_group;" ::: "memory")
#define CPA_WAIT1()  asm volatile("cp.async.wait_group 1;" ::: "memory")
#define CPA_WAIT0()  asm volatile("cp.async.wait_group 0;" ::: "memory")

#define GEMM_AP    24                     // padded row (bf16): LDSM conflict-free
#define GEMM_ARRB  (128 * GEMM_AP * 2)    // bytes per array image
#define GEMM_BUFB  (4 * GEMM_ARRB)        // bytes per stage (Ah,Al,Bh,Bl)
#define GEMM_SMEM  (3 * GEMM_BUFB)        // 3-stage ring = 73728 B

__global__ __launch_bounds__(256, 2)
void gemm_bf16_kernel(const __nv_bfloat16* __restrict__ Ah,
                      const __nv_bfloat16* __restrict__ Al,
                      const __nv_bfloat16* __restrict__ Bh,
                      const __nv_bfloat16* __restrict__ Bl,
                      float* __restrict__ C, int M, int N, int K) {
    constexpr int BK = 16;
    constexpr int AP = GEMM_AP;
    extern __shared__ __nv_bfloat16 sm[];

    int tid  = threadIdx.x;
    int wid  = tid >> 5;
    int lane = tid & 31;
    int wm0  = (wid >> 1) * 32;         // 4x2 warp grid, warp tile 32x64
    int wn0  = (wid & 1) * 64;
    int g    = lane >> 2;
    int tg   = lane & 3;
    int m0   = blockIdx.y * 128;
    int n0   = blockIdx.x * 128;

    float acc[2][8][4];
#pragma unroll
    for (int mt = 0; mt < 2; mt++)
#pragma unroll
        for (int nt = 0; nt < 8; nt++)
#pragma unroll
            for (int j = 0; j < 4; j++) acc[mt][nt][j] = 0.f;

    // ldmatrix per-lane offsets (bf16 elements within a tile image)
    int a_off = (wm0 + (lane & 15)) * AP + ((lane >> 4) << 3);
    int bq = lane >> 3, br = lane & 7;
    int b_off = (wn0 + ((bq >> 1) << 3) + br) * AP + ((bq & 1) << 3);

    // cp.async staging: 1 item (16B) per thread per array
    int r0 = tid >> 1, s0g = tid & 1;
    unsigned sz0a = (m0 + r0 < M) ? 16u : 0u;
    size_t ar0 = (size_t)min(m0 + r0, M - 1) * K + s0g * 8;
    size_t br0 = (size_t)(n0 + r0) * K + s0g * 8;
    unsigned d0 = (unsigned)(r0 * 48 + s0g * 16);

    unsigned smb = (unsigned)__cvta_generic_to_shared(sm);

    auto stage = [&](int buf, int koff) {
        unsigned b = smb + buf * GEMM_BUFB;
        CPA16(b + 0 * GEMM_ARRB + d0, Ah + ar0 + koff, sz0a);
        CPA16(b + 1 * GEMM_ARRB + d0, Al + ar0 + koff, sz0a);
        CPA16(b + 2 * GEMM_ARRB + d0, Bh + br0 + koff, 16u);
        CPA16(b + 3 * GEMM_ARRB + d0, Bl + br0 + koff, 16u);
        CPA_COMMIT();
    };

    int nk = K / BK;                    // >= 2 always (K is 256)
    stage(0, 0);
    stage(1, BK);

    for (int t = 0; t < nk; ++t) {
        CPA_WAIT1();                    // stage t complete (<=1 younger in flight)
        __syncthreads();                // all warps done reading buf (t-1)%3
        if (t + 2 < nk) stage((t + 2) % 3, (t + 2) * BK);

        unsigned abase = smb + (t % 3) * GEMM_BUFB;
        unsigned ah[2][4], alr[2][4];
#pragma unroll
        for (int mt = 0; mt < 2; mt++) {
            LDSM4(ah[mt],  abase + 0 * GEMM_ARRB + (a_off + mt * 16 * AP) * 2);
            LDSM4(alr[mt], abase + 1 * GEMM_ARRB + (a_off + mt * 16 * AP) * 2);
        }
#pragma unroll
        for (int half = 0; half < 2; half++) {
            unsigned bfh[2][4], bfl[2][4];
#pragma unroll
            for (int p = 0; p < 2; p++) {
                unsigned boff = (b_off + (half * 32 + p * 16) * AP) * 2;
                LDSM4(bfh[p], abase + 2 * GEMM_ARRB + boff);
                LDSM4(bfl[p], abase + 3 * GEMM_ARRB + boff);
            }
#pragma unroll
            for (int mt = 0; mt < 2; mt++)
#pragma unroll
                for (int ntl = 0; ntl < 4; ntl++) {
                    int nt = half * 4 + ntl;
                    MMA16(acc[mt][nt], ah[mt],  &bfh[ntl >> 1][(ntl & 1) * 2]);
                    MMA16(acc[mt][nt], ah[mt],  &bfl[ntl >> 1][(ntl & 1) * 2]);
                    MMA16(acc[mt][nt], alr[mt], &bfh[ntl >> 1][(ntl & 1) * 2]);
                }
        }
    }
    CPA_WAIT0();

    // epilogue
#pragma unroll
    for (int mt = 0; mt < 2; mt++) {
        int r = m0 + wm0 + mt * 16 + g;
#pragma unroll
        for (int nt = 0; nt < 8; nt++) {
            int col = n0 + wn0 + nt * 8 + 2 * tg;
            if (r < M)
                *(float2*)(C + (size_t)r * N + col) =
                    make_float2(acc[mt][nt][0], acc[mt][nt][1]);
            if (r + 8 < M)
                *(float2*)(C + (size_t)(r + 8) * N + col) =
                    make_float2(acc[mt][nt][2], acc[mt][nt][3]);
        }
    }
}

// ---------------- attention-logit dot products -------------------------
template <int F>
__global__ void al_kernel(const float* __restrict__ h, const float* __restrict__ asrc,
                          const float* __restrict__ adst, float* __restrict__ als,
                          float* __restrict__ ald, int M) {
    int warp = (blockIdx.x * blockDim.x + threadIdx.x) >> 5;
    int lane = threadIdx.x & 31;
    if (warp >= M) return;
    const float* row = h + (size_t)warp * F;
    float s = 0.f, d = 0.f;
#pragma unroll
    for (int i = lane; i < F; i += 32) {
        float v = row[i];
        s += v * asrc[i];
        d += v * adst[i];
    }
#pragma unroll
    for (int o = 16; o; o >>= 1) {
        s += __shfl_xor_sync(0xffffffffu, s, o);
        d += __shfl_xor_sync(0xffffffffu, d, o);
    }
    if (!lane) {
        als[warp] = s;
        ald[warp] = d;
    }
}

// ---------------- softmax aggregation (one block per (batch,dst)) ------
template <int F, bool SPLIT>
__global__ __launch_bounds__(F)
void agg_kernel(const float* __restrict__ h, const float* __restrict__ als,
                const float* __restrict__ ald, const float* __restrict__ bias,
                float* __restrict__ out,
                __nv_bfloat16* __restrict__ outh, __nv_bfloat16* __restrict__ outl,
                int Nn) {
    constexpr int NW = F / 32;
    constexpr int FQ = F / 4;
    __shared__ float sred[NW];
    __shared__ float sbc;
    __shared__ float sw[DEGCAP + 4];
    __shared__ int   ssrc[DEGCAP + 4];
    __shared__ float4 sred4[4][FQ];

    int bx   = blockIdx.x;
    int v    = bx % Nn;
    int b    = bx / Nn;
    int tid  = threadIdx.x;
    int lane = tid & 31;
    int w    = tid >> 5;
    int begin = v * DEGCAP;
    int deg   = g_count[v];
    int base  = b * Nn;
    float aldv = ald[base + v];

    // pass 1a: segment max
    float lm = -1e30f;
    for (int j = tid; j < deg; j += F) {
        float e = als[base + g_esrc[begin + j]] + aldv;
        e = (e < 0.f) ? 0.2f * e : e;
        lm = fmaxf(lm, e);
    }
#pragma unroll
    for (int o = 16; o; o >>= 1) lm = fmaxf(lm, __shfl_xor_sync(0xffffffffu, lm, o));
    if (!lane) sred[w] = lm;
    __syncthreads();
    if (w == 0) {
        float x = (lane < NW) ? sred[lane] : -1e30f;
#pragma unroll
        for (int o = 16; o; o >>= 1) x = fmaxf(x, __shfl_xor_sync(0xffffffffu, x, o));
        if (!lane) sbc = x;
    }
    __syncthreads();
    float m = sbc;

    // pass 1b: denominator + stash per-edge exp weights in shared
    int degR = (deg + 3) & ~3;
    float ls = 0.f;
    for (int j = tid; j < deg; j += F) {
        int s = g_esrc[begin + j];
        float e = als[base + s] + aldv;
        e = (e < 0.f) ? 0.2f * e : e;
        float ex = __expf(e - m);
        ssrc[j] = s;
        sw[j]   = ex;
        ls += ex;
    }
    if (tid < 4 && deg + tid < degR + 4) {    // zero-pad to multiple of 4
        int j = deg + tid;
        sw[j] = 0.f;
        ssrc[j] = 0;
    }
#pragma unroll
    for (int o = 16; o; o >>= 1) ls += __shfl_xor_sync(0xffffffffu, ls, o);
    if (!lane) sred[w] = ls;
    __syncthreads();
    if (w == 0) {
        float x = (lane < NW) ? sred[lane] : 0.f;
#pragma unroll
        for (int o = 16; o; o >>= 1) x += __shfl_xor_sync(0xffffffffu, x, o);
        if (!lane) sbc = x;
    }
    __syncthreads();
    float inv = 1.f / (sbc + 1e-16f);

    // pass 2: vectorized gather — edge group eg, feature quad fq
    int eg = tid / FQ;
    int fq = tid % FQ;
    float4 a4 = make_float4(0.f, 0.f, 0.f, 0.f);
#pragma unroll 2
    for (int j0 = 0; j0 < deg; j0 += 4) {
        int j = j0 + eg;
        float wj = sw[j];
        float4 hv = *(const float4*)(h + (size_t)(base + ssrc[j]) * F + fq * 4);
        a4.x += wj * hv.x;
        a4.y += wj * hv.y;
        a4.z += wj * hv.z;
        a4.w += wj * hv.w;
    }
    sred4[eg][fq] = a4;
    __syncthreads();

    int q = tid >> 2, c = tid & 3;
    float r = ((const float*)&sred4[0][q])[c] + ((const float*)&sred4[1][q])[c] +
              ((const float*)&sred4[2][q])[c] + ((const float*)&sred4[3][q])[c];
    r = r * inv + bias[tid];
    r = r > 0.f ? r : 0.f;
    size_t oi = (size_t)(base + v) * F + tid;
    if (SPLIT) {
        __nv_bfloat16 hi = __float2bfloat16(r);
        __nv_bfloat16 lo = __float2bfloat16(r - __bfloat162float(hi));
        outh[oi] = hi;
        outl[oi] = lo;
    } else {
        out[oi] = r;
    }
}

// ---------------- launch ----------------------------------------------
extern "C" void kernel_launch(void* const* d_in, const int* in_sizes, int n_in,
                              void* d_out, int out_size) {
    const float* x     = (const float*)d_in[0];
    const void*  edges = d_in[1];
    const float* W0    = (const float*)d_in[2];
    const float* b0    = (const float*)d_in[3];
    const float* asrc0 = (const float*)d_in[4];
    const float* adst0 = (const float*)d_in[5];
    const float* W1    = (const float*)d_in[6];
    const float* b1    = (const float*)d_in[7];
    const float* asrc1 = (const float*)d_in[8];
    const float* adst1 = (const float*)d_in[9];
    float* out = (float*)d_out;

    int F1 = in_sizes[3];            // 256
    int F0 = in_sizes[2] / F1;       // 256
    int F2 = in_sizes[7];            // 128
    int E  = in_sizes[1] / 2;        // 320000
    int M  = in_sizes[0] / F0;       // B*N = 40000
    int Nn = NN;                     // 10000
    int E2 = E + Nn;

    float *p_h0, *p_h1, *p_als, *p_ald;
    __nv_bfloat16 *p_xh, *p_xl, *p_hidh, *p_hidl, *p_wh0, *p_wl0, *p_wh1, *p_wl1;
    cudaGetSymbolAddress((void**)&p_h0,   g_h0);
    cudaGetSymbolAddress((void**)&p_h1,   g_h1);
    cudaGetSymbolAddress((void**)&p_als,  g_als);
    cudaGetSymbolAddress((void**)&p_ald,  g_ald);
    cudaGetSymbolAddress((void**)&p_xh,   g_xh);
    cudaGetSymbolAddress((void**)&p_xl,   g_xl);
    cudaGetSymbolAddress((void**)&p_hidh, g_hidh);
    cudaGetSymbolAddress((void**)&p_hidl, g_hidl);
    cudaGetSymbolAddress((void**)&p_wh0,  g_wh0);
    cudaGetSymbolAddress((void**)&p_wl0,  g_wl0);
    cudaGetSymbolAddress((void**)&p_wh1,  g_wh1);
    cudaGetSymbolAddress((void**)&p_wl1,  g_wl1);

    cudaFuncSetAttribute(gemm_bf16_kernel,
                         cudaFuncAttributeMaxDynamicSharedMemorySize, GEMM_SMEM);

    int mtiles = (M + 127) / 128;
    int n0q = M * F0 / 4, n1q = F1 * F0 / 4, n2q = F2 * F1 / 4;

    // (0) fused splits, (1) zero+detect, (2) CSR build, (3) GEMM0 [profiled]
    split3_kernel<<<(n0q + n1q + n2q + 255) / 256, 256>>>(
        x, p_xh, p_xl, n0q, W0, p_wh0, p_wl0, n1q, W1, p_wh1, p_wl1, n2q);
    zerodetect_kernel<<<(Nn + 255) / 256, 256>>>((const unsigned int*)edges, Nn);
    convert_scatter_kernel<<<(E2 + 255) / 256, 256>>>(edges, E, Nn);

    gemm_bf16_kernel<<<dim3(F1 / 128, mtiles), 256, GEMM_SMEM>>>(
        p_xh, p_xl, p_wh0, p_wl0, p_h0, M, F1, F0);
    al_kernel<256><<<(M * 32 + 255) / 256, 256>>>(p_h0, asrc0, adst0, p_als, p_ald, M);
    agg_kernel<256, true><<<M, 256>>>(p_h0, p_als, p_ald, b0,
                                      nullptr, p_hidh, p_hidl, Nn);

    gemm_bf16_kernel<<<dim3(F2 / 128, mtiles), 256, GEMM_SMEM>>>(
        p_hidh, p_hidl, p_wh1, p_wl1, p_h1, M, F2, F1);
    al_kernel<128><<<(M * 32 + 255) / 256, 256>>>(p_h1, asrc1, adst1, p_als, p_ald, M);
    agg_kernel<128, false><<<M, 128>>>(p_h1, p_als, p_ald, b1,
                                       out, nullptr, nullptr, Nn);
}

// round 9
// speedup vs baseline: 1.0952x; 1.0952x over previous
#include <cuda_runtime.h>
#include <cuda_fp16.h>
#include <cstdint>

// ---------------- problem constants (registry shapes) ----------------
#define NN      10000          // nodes per graph
#define EMAXE   320000         // edges (without self loops)
#define E2MAX   (EMAXE + NN)   // + self loops
#define BBMAX   4              // batch
#define DEGCAP  128            // padded-CSR capacity (max degree ~60 => 12 sigma safe)

// ---------------- device scratch (no allocations allowed) -------------
__device__ int   g_esrc[NN * DEGCAP];   // padded CSR: src per slot
__device__ int   g_count[NN];
__device__ int   g_is64;
__device__ float g_h0 [BBMAX * NN * 256];   // layer0 pre-attention features (fp32)
__device__ float g_h1 [BBMAX * NN * 128];   // layer1 pre-attention features (fp32)
__device__ float g_als[BBMAX * NN];
__device__ float g_ald[BBMAX * NN];
// fp16 operands: x split hi/lo (exact to ~2^-22), W single fp16 (err 2^-12)
__device__ __half g_xh [BBMAX * NN * 256];
__device__ __half g_xl [BBMAX * NN * 256];
__device__ __half g_hidh[BBMAX * NN * 256];  // layer0 output, split
__device__ __half g_hidl[BBMAX * NN * 256];
__device__ __half g_w0 [256 * 256];
__device__ __half g_w1 [128 * 256];

// ---------------- edge preprocessing ----------------------------------

// fused: all blocks zero counts; block 0 lane 0 also detects int64 vs int32
__global__ void zerodetect_kernel(const unsigned int* __restrict__ w, int n) {
    int i = blockIdx.x * blockDim.x + threadIdx.x;
    if (i < n) g_count[i] = 0;
    if (blockIdx.x == 0 && threadIdx.x == 0) {
        int ok = 1;
        for (int k = 1; k < 256; k += 2) {
            if (w[k] != 0u) { ok = 0; break; }
        }
        g_is64 = ok;
    }
}

// one-pass padded-CSR build (incl. self loops)
__global__ void convert_scatter_kernel(const void* __restrict__ edges, int E, int Nn) {
    int i = blockIdx.x * blockDim.x + threadIdx.x;
    int E2 = E + Nn;
    if (i >= E2) return;
    int s, d;
    if (i < E) {
        if (g_is64) {
            const long long* p = (const long long*)edges;
            s = (int)p[i];
            d = (int)p[E + i];
        } else {
            const int* p = (const int*)edges;
            s = p[i];
            d = p[E + i];
        }
    } else {
        s = d = i - E;
    }
    int pos = atomicAdd(&g_count[d], 1);
    g_esrc[d * DEGCAP + pos] = s;
}

// ---------------- fused splits / quantize (x hi/lo, W0, W1) ------------
__global__ void split3_kernel(const float* __restrict__ s0, __half* h0p, __half* l0p, int n0,
                              const float* __restrict__ s1, __half* h1p, int n1,
                              const float* __restrict__ s2, __half* h2p, int n2) {
    int i = blockIdx.x * blockDim.x + threadIdx.x;
    if (i < n0) {
        float4 v = ((const float4*)s0)[i];
        float f[4] = {v.x, v.y, v.z, v.w};
        __half h[4], l[4];
#pragma unroll
        for (int q = 0; q < 4; q++) {
            h[q] = __float2half(f[q]);
            l[q] = __float2half(f[q] - __half2float(h[q]));
        }
        ((uint2*)h0p)[i] = *(uint2*)h;
        ((uint2*)l0p)[i] = *(uint2*)l;
        return;
    }
    i -= n0;
    const float* src; __half* ph;
    if (i < n1)              { src = s1; ph = h1p; }
    else if ((i -= n1) < n2) { src = s2; ph = h2p; }
    else return;
    float4 v = ((const float4*)src)[i];
    __half h[4] = {__float2half(v.x), __float2half(v.y),
                   __float2half(v.z), __float2half(v.w)};
    ((uint2*)ph)[i] = *(uint2*)h;
}

// ---------------- fp16 two-term tensor-core GEMM -----------------------
// C[M][N] = A[M][K] * W[N][K]^T; A pre-split fp16 hi/lo, W single fp16;
// acc += hi*W; acc += lo*W (fp32 accum). ldmatrix + 3-stage cp.async ring,
// 8 warps x (32x64) warp tiles.

#define MMA16(c, a, b)                                                        \
    asm volatile(                                                             \
        "mma.sync.aligned.m16n8k16.row.col.f32.f16.f16.f32 "                  \
        "{%0,%1,%2,%3},{%4,%5,%6,%7},{%8,%9},{%0,%1,%2,%3};"                  \
        : "+f"((c)[0]), "+f"((c)[1]), "+f"((c)[2]), "+f"((c)[3])              \
        : "r"((a)[0]), "r"((a)[1]), "r"((a)[2]), "r"((a)[3]),                 \
          "r"((b)[0]), "r"((b)[1]))

#define LDSM4(R, addr)                                                        \
    asm volatile(                                                             \
        "ldmatrix.sync.aligned.m8n8.x4.shared.b16 {%0,%1,%2,%3}, [%4];"       \
        : "=r"((R)[0]), "=r"((R)[1]), "=r"((R)[2]), "=r"((R)[3])              \
        : "r"(addr))

#define CPA16(dst, src, sz)                                                   \
    asm volatile("cp.async.cg.shared.global [%0], [%1], 16, %2;"              \
                 :: "r"(dst), "l"(src), "r"(sz) : "memory")
#define CPA_COMMIT() asm volatile("cp.async.commit_group;" ::: "memory")
#define CPA_WAIT1()  asm volatile("cp.async.wait_group 1;" ::: "memory")
#define CPA_WAIT0()  asm volatile("cp.async.wait_group 0;" ::: "memory")

#define GEMM_AP    24                     // padded row (fp16): LDSM conflict-free
#define GEMM_ARRB  (128 * GEMM_AP * 2)    // bytes per array image (6144)
#define GEMM_BUFB  (3 * GEMM_ARRB)        // bytes per stage (Ah, Al, B)
#define GEMM_SMEM  (3 * GEMM_BUFB)        // 3-stage ring = 55296 B

__global__ __launch_bounds__(256, 2)
void gemm_fp16_kernel(const __half* __restrict__ Ah,
                      const __half* __restrict__ Al,
                      const __half* __restrict__ Bw,
                      float* __restrict__ C, int M, int N, int K) {
    constexpr int BK = 16;
    constexpr int AP = GEMM_AP;
    extern __shared__ __half sm[];

    int tid  = threadIdx.x;
    int wid  = tid >> 5;
    int lane = tid & 31;
    int wm0  = (wid >> 1) * 32;         // 4x2 warp grid, warp tile 32x64
    int wn0  = (wid & 1) * 64;
    int g    = lane >> 2;
    int tg   = lane & 3;
    int m0   = blockIdx.y * 128;
    int n0   = blockIdx.x * 128;

    float acc[2][8][4];
#pragma unroll
    for (int mt = 0; mt < 2; mt++)
#pragma unroll
        for (int nt = 0; nt < 8; nt++)
#pragma unroll
            for (int j = 0; j < 4; j++) acc[mt][nt][j] = 0.f;

    // ldmatrix per-lane offsets (fp16 elements within a tile image)
    int a_off = (wm0 + (lane & 15)) * AP + ((lane >> 4) << 3);
    int bq = lane >> 3, br = lane & 7;
    int b_off = (wn0 + ((bq >> 1) << 3) + br) * AP + ((bq & 1) << 3);

    // cp.async staging: 1 item (16B) per thread per array
    int r0 = tid >> 1, s0g = tid & 1;
    unsigned sz0a = (m0 + r0 < M) ? 16u : 0u;
    size_t ar0 = (size_t)min(m0 + r0, M - 1) * K + s0g * 8;
    size_t br0 = (size_t)(n0 + r0) * K + s0g * 8;
    unsigned d0 = (unsigned)(r0 * 48 + s0g * 16);

    unsigned smb = (unsigned)__cvta_generic_to_shared(sm);

    auto stage = [&](int buf, int koff) {
        unsigned b = smb + buf * GEMM_BUFB;
        CPA16(b + 0 * GEMM_ARRB + d0, Ah + ar0 + koff, sz0a);
        CPA16(b + 1 * GEMM_ARRB + d0, Al + ar0 + koff, sz0a);
        CPA16(b + 2 * GEMM_ARRB + d0, Bw + br0 + koff, 16u);
        CPA_COMMIT();
    };

    int nk = K / BK;
    stage(0, 0);
    stage(1, BK);

    for (int t = 0; t < nk; ++t) {
        CPA_WAIT1();                    // stage t complete
        __syncthreads();                // all warps done with buf (t-1)%3
        if (t + 2 < nk) stage((t + 2) % 3, (t + 2) * BK);

        unsigned abase = smb + (t % 3) * GEMM_BUFB;
        unsigned ah[2][4], alr[2][4];
#pragma unroll
        for (int mt = 0; mt < 2; mt++) {
            LDSM4(ah[mt],  abase + 0 * GEMM_ARRB + (a_off + mt * 16 * AP) * 2);
            LDSM4(alr[mt], abase + 1 * GEMM_ARRB + (a_off + mt * 16 * AP) * 2);
        }
#pragma unroll
        for (int half = 0; half < 2; half++) {
            unsigned bf[2][4];
#pragma unroll
            for (int p = 0; p < 2; p++) {
                unsigned boff = (b_off + (half * 32 + p * 16) * AP) * 2;
                LDSM4(bf[p], abase + 2 * GEMM_ARRB + boff);
            }
#pragma unroll
            for (int mt = 0; mt < 2; mt++)
#pragma unroll
                for (int ntl = 0; ntl < 4; ntl++) {
                    int nt = half * 4 + ntl;
                    MMA16(acc[mt][nt], ah[mt],  &bf[ntl >> 1][(ntl & 1) * 2]);
                    MMA16(acc[mt][nt], alr[mt], &bf[ntl >> 1][(ntl & 1) * 2]);
                }
        }
    }
    CPA_WAIT0();

    // epilogue
#pragma unroll
    for (int mt = 0; mt < 2; mt++) {
        int r = m0 + wm0 + mt * 16 + g;
#pragma unroll
        for (int nt = 0; nt < 8; nt++) {
            int col = n0 + wn0 + nt * 8 + 2 * tg;
            if (r < M)
                *(float2*)(C + (size_t)r * N + col) =
                    make_float2(acc[mt][nt][0], acc[mt][nt][1]);
            if (r + 8 < M)
                *(float2*)(C + (size_t)(r + 8) * N + col) =
                    make_float2(acc[mt][nt][2], acc[mt][nt][3]);
        }
    }
}

// ---------------- attention-logit dot products -------------------------
template <int F>
__global__ void al_kernel(const float* __restrict__ h, const float* __restrict__ asrc,
                          const float* __restrict__ adst, float* __restrict__ als,
                          float* __restrict__ ald, int M) {
    int warp = (blockIdx.x * blockDim.x + threadIdx.x) >> 5;
    int lane = threadIdx.x & 31;
    if (warp >= M) return;
    const float* row = h + (size_t)warp * F;
    float s = 0.f, d = 0.f;
#pragma unroll
    for (int i = lane; i < F; i += 32) {
        float v = row[i];
        s += v * asrc[i];
        d += v * adst[i];
    }
#pragma unroll
    for (int o = 16; o; o >>= 1) {
        s += __shfl_xor_sync(0xffffffffu, s, o);
        d += __shfl_xor_sync(0xffffffffu, d, o);
    }
    if (!lane) {
        als[warp] = s;
        ald[warp] = d;
    }
}

// ---------------- softmax aggregation (one block per (batch,dst)) ------
template <int F, bool SPLIT>
__global__ __launch_bounds__(F)
void agg_kernel(const float* __restrict__ h, const float* __restrict__ als,
                const float* __restrict__ ald, const float* __restrict__ bias,
                float* __restrict__ out,
                __half* __restrict__ outh, __half* __restrict__ outl,
                int Nn) {
    constexpr int NW = F / 32;
    constexpr int FQ = F / 4;
    __shared__ float sred[NW];
    __shared__ float sbc;
    __shared__ float sw[DEGCAP + 4];
    __shared__ int   ssrc[DEGCAP + 4];
    __shared__ float4 sred4[4][FQ];

    int bx   = blockIdx.x;
    int v    = bx % Nn;
    int b    = bx / Nn;
    int tid  = threadIdx.x;
    int lane = tid & 31;
    int w    = tid >> 5;
    int begin = v * DEGCAP;
    int deg   = g_count[v];
    int base  = b * Nn;
    float aldv = ald[base + v];

    // pass 1a: segment max
    float lm = -1e30f;
    for (int j = tid; j < deg; j += F) {
        float e = als[base + g_esrc[begin + j]] + aldv;
        e = (e < 0.f) ? 0.2f * e : e;
        lm = fmaxf(lm, e);
    }
#pragma unroll
    for (int o = 16; o; o >>= 1) lm = fmaxf(lm, __shfl_xor_sync(0xffffffffu, lm, o));
    if (!lane) sred[w] = lm;
    __syncthreads();
    if (w == 0) {
        float x = (lane < NW) ? sred[lane] : -1e30f;
#pragma unroll
        for (int o = 16; o; o >>= 1) x = fmaxf(x, __shfl_xor_sync(0xffffffffu, x, o));
        if (!lane) sbc = x;
    }
    __syncthreads();
    float m = sbc;

    // pass 1b: denominator + stash per-edge exp weights in shared
    int degR = (deg + 3) & ~3;
    float ls = 0.f;
    for (int j = tid; j < deg; j += F) {
        int s = g_esrc[begin + j];
        float e = als[base + s] + aldv;
        e = (e < 0.f) ? 0.2f * e : e;
        float ex = __expf(e - m);
        ssrc[j] = s;
        sw[j]   = ex;
        ls += ex;
    }
    if (tid < 4 && deg + tid < degR + 4) {    // zero-pad to multiple of 4
        int j = deg + tid;
        sw[j] = 0.f;
        ssrc[j] = 0;
    }
#pragma unroll
    for (int o = 16; o; o >>= 1) ls += __shfl_xor_sync(0xffffffffu, ls, o);
    if (!lane) sred[w] = ls;
    __syncthreads();
    if (w == 0) {
        float x = (lane < NW) ? sred[lane] : 0.f;
#pragma unroll
        for (int o = 16; o; o >>= 1) x += __shfl_xor_sync(0xffffffffu, x, o);
        if (!lane) sbc = x;
    }
    __syncthreads();
    float inv = 1.f / (sbc + 1e-16f);

    // pass 2: vectorized gather — edge group eg, feature quad fq
    int eg = tid / FQ;
    int fq = tid % FQ;
    float4 a4 = make_float4(0.f, 0.f, 0.f, 0.f);
#pragma unroll 2
    for (int j0 = 0; j0 < deg; j0 += 4) {
        int j = j0 + eg;
        float wj = sw[j];
        float4 hv = *(const float4*)(h + (size_t)(base + ssrc[j]) * F + fq * 4);
        a4.x += wj * hv.x;
        a4.y += wj * hv.y;
        a4.z += wj * hv.z;
        a4.w += wj * hv.w;
    }
    sred4[eg][fq] = a4;
    __syncthreads();

    int q = tid >> 2, c = tid & 3;
    float r = ((const float*)&sred4[0][q])[c] + ((const float*)&sred4[1][q])[c] +
              ((const float*)&sred4[2][q])[c] + ((const float*)&sred4[3][q])[c];
    r = r * inv + bias[tid];
    r = r > 0.f ? r : 0.f;
    size_t oi = (size_t)(base + v) * F + tid;
    if (SPLIT) {
        __half hi = __float2half(r);
        __half lo = __float2half(r - __half2float(hi));
        outh[oi] = hi;
        outl[oi] = lo;
    } else {
        out[oi] = r;
    }
}

// ---------------- launch ----------------------------------------------
extern "C" void kernel_launch(void* const* d_in, const int* in_sizes, int n_in,
                              void* d_out, int out_size) {
    const float* x     = (const float*)d_in[0];
    const void*  edges = d_in[1];
    const float* W0    = (const float*)d_in[2];
    const float* b0    = (const float*)d_in[3];
    const float* asrc0 = (const float*)d_in[4];
    const float* adst0 = (const float*)d_in[5];
    const float* W1    = (const float*)d_in[6];
    const float* b1    = (const float*)d_in[7];
    const float* asrc1 = (const float*)d_in[8];
    const float* adst1 = (const float*)d_in[9];
    float* out = (float*)d_out;

    int F1 = in_sizes[3];            // 256
    int F0 = in_sizes[2] / F1;       // 256
    int F2 = in_sizes[7];            // 128
    int E  = in_sizes[1] / 2;        // 320000
    int M  = in_sizes[0] / F0;       // B*N = 40000
    int Nn = NN;                     // 10000
    int E2 = E + Nn;

    float *p_h0, *p_h1, *p_als, *p_ald;
    __half *p_xh, *p_xl, *p_hidh, *p_hidl, *p_w0, *p_w1;
    cudaGetSymbolAddress((void**)&p_h0,   g_h0);
    cudaGetSymbolAddress((void**)&p_h1,   g_h1);
    cudaGetSymbolAddress((void**)&p_als,  g_als);
    cudaGetSymbolAddress((void**)&p_ald,  g_ald);
    cudaGetSymbolAddress((void**)&p_xh,   g_xh);
    cudaGetSymbolAddress((void**)&p_xl,   g_xl);
    cudaGetSymbolAddress((void**)&p_hidh, g_hidh);
    cudaGetSymbolAddress((void**)&p_hidl, g_hidl);
    cudaGetSymbolAddress((void**)&p_w0,   g_w0);
    cudaGetSymbolAddress((void**)&p_w1,   g_w1);

    cudaFuncSetAttribute(gemm_fp16_kernel,
                         cudaFuncAttributeMaxDynamicSharedMemorySize, GEMM_SMEM);

    int mtiles = (M + 127) / 128;
    int n0q = M * F0 / 4, n1q = F1 * F0 / 4, n2q = F2 * F1 / 4;

    // (0) fused splits, (1) zero+detect, (2) CSR build, (3) GEMM0 [profiled]
    split3_kernel<<<(n0q + n1q + n2q + 255) / 256, 256>>>(
        x, p_xh, p_xl, n0q, W0, p_w0, n1q, W1, p_w1, n2q);
    zerodetect_kernel<<<(Nn + 255) / 256, 256>>>((const unsigned int*)edges, Nn);
    convert_scatter_kernel<<<(E2 + 255) / 256, 256>>>(edges, E, Nn);

    gemm_fp16_kernel<<<dim3(F1 / 128, mtiles), 256, GEMM_SMEM>>>(
        p_xh, p_xl, p_w0, p_h0, M, F1, F0);
    al_kernel<256><<<(M * 32 + 255) / 256, 256>>>(p_h0, asrc0, adst0, p_als, p_ald, M);
    agg_kernel<256, true><<<M, 256>>>(p_h0, p_als, p_ald, b0,
                                      nullptr, p_hidh, p_hidl, Nn);

    gemm_fp16_kernel<<<dim3(F2 / 128, mtiles), 256, GEMM_SMEM>>>(
        p_hidh, p_hidl, p_w1, p_h1, M, F2, F1);
    al_kernel<128><<<(M * 32 + 255) / 256, 256>>>(p_h1, asrc1, adst1, p_als, p_ald, M);
    agg_kernel<128, false><<<M, 128>>>(p_h1, p_als, p_ald, b1,
                                       out, nullptr, nullptr, Nn);
}